// round 9
// baseline (speedup 1.0000x reference)
#include <cuda_runtime.h>
#include <cstdint>
#include <cstddef>

// ---------------------------------------------------------------------------
// NonOverlappingConv1d as GEMM, legacy tf32 mma.sync.m16n8k8 (tcgen05 PTX is
// rejected by this harness's ptxas target — verified R8).
//
//   out[b,o,p] = sum_kidx (W[o][kidx]/sqrt(128)) * x[b, kidx>>1, 2p+(kidx&1)]
//
// A (weights): fragment-order SMEM, staged ONCE per CTA, scale pre-folded,
//              conflict-free LDS.128, 128 KB, no padding.
// B (x):       built DIRECTLY from gmem — the m16n8k8 B-fragment lane map
//              (lane=4n+q -> B[n][q], B[n][q+4]) turns x's (2p+k) interleave
//              into 2 fully-coalesced LDG.32 warp requests per fragment
//              (2 rows x 64B contiguous). No STS, no LDS, no mainloop syncs.
// Warp tile 64(o) x 64(p); CTA 128 x 256; 8 warps; grid (16,32)=512 CTAs.
// ---------------------------------------------------------------------------

namespace {
constexpr int kCin = 128, kDin = 8192, kP = 4096, kO = 128, kK = 256;
constexpr int kTileP = 256;
constexpr int kThreads = 256;
constexpr int A_FLOATS = kO * kK;          // 32768 floats
constexpr int SMEM_BYTES = A_FLOATS * 4;   // 131072 B
}  // namespace

__device__ __forceinline__ float to_tf32(float x) {
  uint32_t u;
  asm("cvt.rna.tf32.f32 %0, %1;" : "=r"(u) : "f"(x));
  return __uint_as_float(u);
}
__device__ __forceinline__ uint32_t tf32u(float x) {
  uint32_t u;
  asm("cvt.rna.tf32.f32 %0, %1;" : "=r"(u) : "f"(x));
  return u;
}

__device__ __forceinline__ void mma_tf32(float d[4], const uint32_t a[4],
                                         const uint32_t b[2]) {
  asm volatile(
      "mma.sync.aligned.m16n8k8.row.col.f32.tf32.tf32.f32 "
      "{%0,%1,%2,%3}, {%4,%5,%6,%7}, {%8,%9}, {%0,%1,%2,%3};"
      : "+f"(d[0]), "+f"(d[1]), "+f"(d[2]), "+f"(d[3])
      : "r"(a[0]), "r"(a[1]), "r"(a[2]), "r"(a[3]), "r"(b[0]), "r"(b[1]));
}

__global__ __launch_bounds__(kThreads, 1)
void conv1d_tf32_direct(const float* __restrict__ x,
                        const float* __restrict__ w,
                        float* __restrict__ out) {
  extern __shared__ float sA[];

  const int tid = threadIdx.x;
  const int lane = tid & 31;
  const int wid = tid >> 5;
  const int b = blockIdx.y;
  const int p0 = blockIdx.x * kTileP;

  // ------------------------------------------------------------------
  // Stage A (128x256 weights) once, fragment order, scale pre-folded.
  // Slot for (o,kidx): mt=o>>4, kt=kidx>>3, r=o&15, c=kidx&7
  //   lane=(r&7)*4+(c&3);  reg=(r>>3)+((c>>2)<<1)
  //   float offset = (mt*32+kt)*128 + lane*4 + reg
  // ------------------------------------------------------------------
  const float scale = 0.08838834764831845f;   // 1/sqrt(128)
  #pragma unroll
  for (int it = 0; it < 32; ++it) {
    int lin = it * kThreads + tid;
    int o = lin >> 6;            // 64 float4 per weight row
    int j = lin & 63;
    float4 w4 = *reinterpret_cast<const float4*>(w + o * kK + 4 * j);
    float v[4] = {to_tf32(w4.x * scale), to_tf32(w4.y * scale),
                  to_tf32(w4.z * scale), to_tf32(w4.w * scale)};
    int mt = o >> 4, r = o & 15, kt = j >> 1;
    float* base = sA + (mt * 32 + kt) * 128;
    #pragma unroll
    for (int e = 0; e < 4; ++e) {
      int c = (4 * j + e) & 7;
      int ln = (r & 7) * 4 + (c & 3);
      int rg = (r >> 3) + ((c >> 2) << 1);
      base[ln * 4 + rg] = v[e];
    }
  }
  __syncthreads();

  // ------------------------------------------------------------------
  // Warp tiling: 8 warps = 2(m) x 4(n); warp tile 64(o) x 64(p).
  // ------------------------------------------------------------------
  const int wm = (wid >> 2) * 64;        // 0 or 64
  const int wn = (wid & 3) * 64;         // 0,64,128,192
  const int gid = lane >> 2, tq = lane & 3;

  float acc[4][8][4];
  #pragma unroll
  for (int i = 0; i < 4; ++i)
    #pragma unroll
    for (int j2 = 0; j2 < 8; ++j2)
      #pragma unroll
      for (int r2 = 0; r2 < 4; ++r2) acc[i][j2][r2] = 0.f;

  // B fragment gmem base for this lane:
  //   b0(kt,nt) = x[b, kt*4 + (tq>>1),     2*(p0+wn+nt*8+gid) + (tq&1)]
  //   b1(kt,nt) = x[b, kt*4 + (tq>>1) + 2, same column]
  const float* xb = x + ((size_t)b * kCin + (size_t)(tq >> 1)) * kDin +
                    2 * (p0 + wn + gid) + (tq & 1);
  const float* sAw = sA + (wm >> 4) * 32 * 128;

  float braw[8][2];
  #pragma unroll
  for (int nt = 0; nt < 8; ++nt) {
    braw[nt][0] = __ldg(xb + nt * 16);
    braw[nt][1] = __ldg(xb + 2 * kDin + nt * 16);
  }

  #pragma unroll 4
  for (int kt = 0; kt < 32; ++kt) {
    // A fragments for this k-step (conflict-free LDS.128).
    uint32_t afr[4][4];
    #pragma unroll
    for (int mt2 = 0; mt2 < 4; ++mt2) {
      uint4 av = *reinterpret_cast<const uint4*>(
          sAw + (mt2 * 32 + kt) * 128 + lane * 4);
      afr[mt2][0] = av.x; afr[mt2][1] = av.y;
      afr[mt2][2] = av.z; afr[mt2][3] = av.w;
    }
    // Round current B to tf32.
    uint32_t bfr[8][2];
    #pragma unroll
    for (int nt = 0; nt < 8; ++nt) {
      bfr[nt][0] = tf32u(braw[nt][0]);
      bfr[nt][1] = tf32u(braw[nt][1]);
    }
    // Prefetch next k-step's B from gmem (hidden under 32 MMAs).
    if (kt < 31) {
      const float* xn = xb + (size_t)((kt + 1) * 4) * kDin;
      #pragma unroll
      for (int nt = 0; nt < 8; ++nt) {
        braw[nt][0] = __ldg(xn + nt * 16);
        braw[nt][1] = __ldg(xn + 2 * kDin + nt * 16);
      }
    }
    // 32 MMAs.
    #pragma unroll
    for (int mt2 = 0; mt2 < 4; ++mt2)
      #pragma unroll
      for (int nt = 0; nt < 8; ++nt)
        mma_tf32(acc[mt2][nt], afr[mt2], bfr[nt]);
  }

  // ------------------------------------------------------------------
  // Epilogue (scale already folded into A): float2 stores.
  // D frag: c0:(g,2tq) c1:(g,2tq+1) c2:(g+8,2tq) c3:(g+8,2tq+1)
  // ------------------------------------------------------------------
  float* ob = out + (size_t)b * kO * kP;
  #pragma unroll
  for (int mt2 = 0; mt2 < 4; ++mt2) {
    int o0 = wm + mt2 * 16 + gid;
    #pragma unroll
    for (int nt = 0; nt < 8; ++nt) {
      int p = p0 + wn + nt * 8 + 2 * tq;
      *reinterpret_cast<float2*>(ob + (size_t)o0 * kP + p) =
          make_float2(acc[mt2][nt][0], acc[mt2][nt][1]);
      *reinterpret_cast<float2*>(ob + (size_t)(o0 + 8) * kP + p) =
          make_float2(acc[mt2][nt][2], acc[mt2][nt][3]);
    }
  }
}

extern "C" void kernel_launch(void* const* d_in, const int* in_sizes, int n_in,
                              void* d_out, int out_size) {
  const float* x = (const float*)d_in[0];
  const float* w = (const float*)d_in[1];
  if (n_in >= 2 && in_sizes[0] == kO * kK) {   // defensive operand id by size
    const float* t = x; x = w; w = t;
  }
  (void)out_size;

  cudaFuncSetAttribute(conv1d_tf32_direct,
                       cudaFuncAttributeMaxDynamicSharedMemorySize, SMEM_BYTES);

  dim3 grid(kP / kTileP, 32);   // (16, 32) = 512 CTAs
  conv1d_tf32_direct<<<grid, kThreads, SMEM_BYTES>>>(x, w, (float*)d_out);
}

// round 10
// speedup vs baseline: 1.1248x; 1.1248x over previous
#include <cuda_runtime.h>
#include <cstdint>
#include <cstddef>

// ---------------------------------------------------------------------------
// NonOverlappingConv1d as GEMM, tf32 mma.sync.m16n8k8 (tcgen05 unavailable in
// this harness's ptxas target, verified R8).
//
//   out[b,o,p] = sum_kidx (W[o][kidx]/sqrt(128)) * x[b, kidx>>1, 2p+(kidx&1)]
//
// A (weights): fragment-order SMEM, staged once/CTA, scale folded, LDS.128.
// B (x):       cp.async.cg 16B into row-major SMEM (rows = c_local, 2KB each,
//              odd rows XOR 64B), 2-stage pipeline over 8 K-chunks of 32.
//              Fragment build = 2 conflict-free LDS.32 + cvt.rna.tf32.
// Warp tile 64(o) x 64(p); CTA 128 x 256; 8 warps; grid (16,32)=512.
// ---------------------------------------------------------------------------

namespace {
constexpr int kCin = 128, kDin = 8192, kP = 4096, kO = 128, kK = 256;
constexpr int TILE_P = 256;
constexpr int THREADS = 256;
constexpr int NCH = 8;                     // K-chunks of 32 kidx (16 c-rows)
constexpr int ROWB = TILE_P * 2 * 4;       // 2048 B per B row (512 floats)
constexpr uint32_t A_BYTES = 131072u;      // 128 x 256 fp32
constexpr uint32_t B_STAGE = 16u * ROWB;   // 32768 B
constexpr uint32_t SMEM_BYTES = A_BYTES + 2u * B_STAGE;   // 196608
}  // namespace

__device__ __forceinline__ uint32_t smem_u32(const void* p) {
  uint32_t a;
  asm("{ .reg .u64 t; cvta.to.shared.u64 t, %1; cvt.u32.u64 %0, t; }"
      : "=r"(a) : "l"(p));
  return a;
}
__device__ __forceinline__ float to_tf32(float x) {
  uint32_t u;
  asm("cvt.rna.tf32.f32 %0, %1;" : "=r"(u) : "f"(x));
  return __uint_as_float(u);
}
__device__ __forceinline__ uint32_t tf32u(float x) {
  uint32_t u;
  asm("cvt.rna.tf32.f32 %0, %1;" : "=r"(u) : "f"(x));
  return u;
}
__device__ __forceinline__ void cp16(uint32_t dst, const void* src) {
  asm volatile("cp.async.cg.shared.global [%0], [%1], 16;"
               :: "r"(dst), "l"(src) : "memory");
}
__device__ __forceinline__ void cp_commit() {
  asm volatile("cp.async.commit_group;" ::: "memory");
}
template <int N>
__device__ __forceinline__ void cp_wait() {
  asm volatile("cp.async.wait_group %0;" :: "n"(N) : "memory");
}
__device__ __forceinline__ float lds32(uint32_t a) {
  float f;
  asm volatile("ld.shared.f32 %0, [%1];" : "=f"(f) : "r"(a));
  return f;
}
__device__ __forceinline__ void mma_tf32(float d[4], const uint32_t a[4],
                                         const uint32_t b[2]) {
  asm volatile(
      "mma.sync.aligned.m16n8k8.row.col.f32.tf32.tf32.f32 "
      "{%0,%1,%2,%3}, {%4,%5,%6,%7}, {%8,%9}, {%0,%1,%2,%3};"
      : "+f"(d[0]), "+f"(d[1]), "+f"(d[2]), "+f"(d[3])
      : "r"(a[0]), "r"(a[1]), "r"(a[2]), "r"(a[3]), "r"(b[0]), "r"(b[1]));
}

__global__ __launch_bounds__(THREADS, 1)
void conv1d_tf32_pipe(const float* __restrict__ x,
                      const float* __restrict__ w,
                      float* __restrict__ out) {
  extern __shared__ char smem[];
  float* sA = reinterpret_cast<float*>(smem);
  const uint32_t sBu = smem_u32(smem) + A_BYTES;

  const int tid = threadIdx.x;
  const int lane = tid & 31;
  const int wid = tid >> 5;
  const int b = blockIdx.y;
  const int p0 = blockIdx.x * TILE_P;

  // ------------------------------------------------------------------
  // Stage A (128x256 weights) once, fragment order, 1/sqrt(128) folded.
  // Slot (o,kidx): mt=o>>4, kt=kidx>>3, r=o&15, c=kidx&7
  //   lane=(r&7)*4+(c&3), reg=(r>>3)+((c>>2)<<1)
  //   float offset = (mt*32+kt)*128 + lane*4 + reg
  // ------------------------------------------------------------------
  const float scale = 0.08838834764831845f;
  #pragma unroll
  for (int it = 0; it < 32; ++it) {
    int lin = it * THREADS + tid;
    int o = lin >> 6;
    int j = lin & 63;
    float4 w4 = *reinterpret_cast<const float4*>(w + o * kK + 4 * j);
    float v[4] = {to_tf32(w4.x * scale), to_tf32(w4.y * scale),
                  to_tf32(w4.z * scale), to_tf32(w4.w * scale)};
    int mt = o >> 4, r = o & 15, kt = j >> 1;
    float* base = sA + (mt * 32 + kt) * 128;
    #pragma unroll
    for (int e = 0; e < 4; ++e) {
      int c = (4 * j + e) & 7;
      int ln = (r & 7) * 4 + (c & 3);
      int rg = (r >> 3) + ((c >> 2) << 1);
      base[ln * 4 + rg] = v[e];
    }
  }

  // ------------------------------------------------------------------
  // B chunk loader: chunk ch = c rows [16ch,16ch+16), 512 floats each.
  // dst row-local byte = col16*16, XOR 64 on odd rows.
  // ------------------------------------------------------------------
  const int ld_row_off = tid >> 7;            // 0 or 1
  const int ld_c16 = tid & 127;
  auto load_chunk = [&](int ch, int buf) {
    const float* xb =
        x + ((size_t)(b * kCin + ch * 16 + ld_row_off)) * kDin + 2 * p0 +
        4 * ld_c16;
    uint32_t d0 = sBu + (uint32_t)buf * B_STAGE +
                  (uint32_t)ld_row_off * ROWB +
                  ((uint32_t)(ld_c16 * 16) ^ ((uint32_t)(ld_row_off & 1) << 6));
    #pragma unroll
    for (int q = 0; q < 8; ++q) {     // rows ld_row_off + 2q
      cp16(d0 + (uint32_t)(2 * q) * ROWB, xb + (size_t)(2 * q) * kDin);
    }
    cp_commit();
  };

  // ------------------------------------------------------------------
  // Warp tiling: 8 warps = 2(m) x 4(n), warp tile 64 x 64.
  // ------------------------------------------------------------------
  const int wm = (wid >> 2) * 64;
  const int wn = (wid & 3) * 64;
  const int gid = lane >> 2, tq = lane & 3;
  const float* sAw = sA + (wm >> 4) * 32 * 128;

  float acc[4][8][4];
  #pragma unroll
  for (int i = 0; i < 4; ++i)
    #pragma unroll
    for (int j2 = 0; j2 < 8; ++j2)
      #pragma unroll
      for (int r2 = 0; r2 < 4; ++r2) acc[i][j2][r2] = 0.f;

  // Per-lane B address pieces. Fragment (nt,k8):
  //   reg0: row 4k8+(tq>>1),   pos 2*(wn+8nt+gid)+(tq&1)
  //   reg1: row 4k8+(tq>>1)+2, same pos.   XOR 64 iff row odd ((tq>>1)&1).
  const uint32_t bpar = ((uint32_t)(tq >> 1) & 1u) << 6;
  const uint32_t brow0 = (uint32_t)(tq >> 1) * ROWB;
  const uint32_t bq0 = (uint32_t)(8 * (wn + gid) + 4 * (tq & 1));

  auto compute_chunk = [&](int ch, int buf) {
    const uint32_t bb = sBu + (uint32_t)buf * B_STAGE + brow0;
    #pragma unroll
    for (int k8 = 0; k8 < 4; ++k8) {
      const int kt = ch * 4 + k8;
      uint32_t afr[4][4];
      #pragma unroll
      for (int mt2 = 0; mt2 < 4; ++mt2) {
        uint4 av = *reinterpret_cast<const uint4*>(
            sAw + (mt2 * 32 + kt) * 128 + lane * 4);
        afr[mt2][0] = av.x; afr[mt2][1] = av.y;
        afr[mt2][2] = av.z; afr[mt2][3] = av.w;
      }
      const uint32_t rb = bb + (uint32_t)(4 * k8) * ROWB;
      uint32_t bfr[8][2];
      #pragma unroll
      for (int nt = 0; nt < 8; ++nt) {
        uint32_t loc = (bq0 + (uint32_t)(64 * nt)) ^ bpar;
        bfr[nt][0] = tf32u(lds32(rb + loc));
        bfr[nt][1] = tf32u(lds32(rb + 2u * ROWB + loc));
      }
      #pragma unroll
      for (int mt2 = 0; mt2 < 4; ++mt2)
        #pragma unroll
        for (int nt = 0; nt < 8; ++nt)
          mma_tf32(acc[mt2][nt], afr[mt2], bfr[nt]);
    }
  };

  // ------------------------------------------------------------------
  // 2-stage cp.async pipeline over 8 chunks.
  // ------------------------------------------------------------------
  load_chunk(0, 0);
  __syncthreads();      // A staging visible to all (and pipeline start)

  #pragma unroll 1
  for (int ch = 0; ch < NCH; ++ch) {
    if (ch + 1 < NCH) {
      load_chunk(ch + 1, (ch + 1) & 1);
      cp_wait<1>();
    } else {
      cp_wait<0>();
    }
    __syncthreads();
    compute_chunk(ch, ch & 1);
    __syncthreads();
  }

  // ------------------------------------------------------------------
  // Epilogue (scale already folded): float2 stores.
  // ------------------------------------------------------------------
  float* ob = out + (size_t)b * kO * kP;
  #pragma unroll
  for (int mt2 = 0; mt2 < 4; ++mt2) {
    int o0 = wm + mt2 * 16 + gid;
    #pragma unroll
    for (int nt = 0; nt < 8; ++nt) {
      int p = p0 + wn + nt * 8 + 2 * tq;
      *reinterpret_cast<float2*>(ob + (size_t)o0 * kP + p) =
          make_float2(acc[mt2][nt][0], acc[mt2][nt][1]);
      *reinterpret_cast<float2*>(ob + (size_t)(o0 + 8) * kP + p) =
          make_float2(acc[mt2][nt][2], acc[mt2][nt][3]);
    }
  }
}

extern "C" void kernel_launch(void* const* d_in, const int* in_sizes, int n_in,
                              void* d_out, int out_size) {
  const float* x = (const float*)d_in[0];
  const float* w = (const float*)d_in[1];
  if (n_in >= 2 && in_sizes[0] == kO * kK) {   // defensive operand id by size
    const float* t = x; x = w; w = t;
  }
  (void)out_size;

  cudaFuncSetAttribute(conv1d_tf32_pipe,
                       cudaFuncAttributeMaxDynamicSharedMemorySize, SMEM_BYTES);

  dim3 grid(kP / TILE_P, 32);   // (16, 32) = 512 CTAs
  conv1d_tf32_pipe<<<grid, THREADS, SMEM_BYTES>>>(x, w, (float*)d_out);
}

// round 11
// speedup vs baseline: 1.2870x; 1.1442x over previous
#include <cuda_runtime.h>
#include <cstdint>
#include <cstddef>

// ---------------------------------------------------------------------------
// NonOverlappingConv1d as GEMM, tf32 mma.sync.m16n8k8 (tcgen05 PTX rejected by
// this harness's ptxas target — verified R8).
//
//   out[b,o,p] = sum_kidx (W[o][kidx]/sqrt(128)) * x[b, kidx>>1, 2p+(kidx&1)]
//
// R11 change vs R10: 512 threads / 16 warps (warp tile 64x32, grid 2m x 8n).
// All pipes were <52% busy at 8 warps/SM -> latency-bound; double the warps,
// halve per-thread acc registers (64), keep the cp.async B path.
//
// A (weights): fragment-order SMEM, staged once/CTA, scale folded, LDS.128.
// B (x): cp.async.cg 16B -> row-major SMEM (2KB rows, odd rows XOR 64B),
//        2-stage pipeline over 8 K-chunks of 32 kidx. Fragments via 2
//        conflict-free LDS.32 + cvt.rna.tf32.
// CTA 128(o) x 256(p); grid (16,32)=512.
// ---------------------------------------------------------------------------

namespace {
constexpr int kCin = 128, kDin = 8192, kP = 4096, kO = 128, kK = 256;
constexpr int TILE_P = 256;
constexpr int THREADS = 512;
constexpr int NCH = 8;                     // K-chunks of 32 kidx (16 c-rows)
constexpr int ROWB = TILE_P * 2 * 4;       // 2048 B per B row (512 floats)
constexpr uint32_t A_BYTES = 131072u;      // 128 x 256 fp32
constexpr uint32_t B_STAGE = 16u * ROWB;   // 32768 B
constexpr uint32_t SMEM_BYTES = A_BYTES + 2u * B_STAGE;   // 196608
}  // namespace

__device__ __forceinline__ uint32_t smem_u32(const void* p) {
  uint32_t a;
  asm("{ .reg .u64 t; cvta.to.shared.u64 t, %1; cvt.u32.u64 %0, t; }"
      : "=r"(a) : "l"(p));
  return a;
}
__device__ __forceinline__ float to_tf32(float x) {
  uint32_t u;
  asm("cvt.rna.tf32.f32 %0, %1;" : "=r"(u) : "f"(x));
  return __uint_as_float(u);
}
__device__ __forceinline__ uint32_t tf32u(float x) {
  uint32_t u;
  asm("cvt.rna.tf32.f32 %0, %1;" : "=r"(u) : "f"(x));
  return u;
}
__device__ __forceinline__ void cp16(uint32_t dst, const void* src) {
  asm volatile("cp.async.cg.shared.global [%0], [%1], 16;"
               :: "r"(dst), "l"(src) : "memory");
}
__device__ __forceinline__ void cp_commit() {
  asm volatile("cp.async.commit_group;" ::: "memory");
}
template <int N>
__device__ __forceinline__ void cp_wait() {
  asm volatile("cp.async.wait_group %0;" :: "n"(N) : "memory");
}
__device__ __forceinline__ float lds32(uint32_t a) {
  float f;
  asm volatile("ld.shared.f32 %0, [%1];" : "=f"(f) : "r"(a));
  return f;
}
__device__ __forceinline__ void mma_tf32(float d[4], const uint32_t a[4],
                                         const uint32_t b[2]) {
  asm volatile(
      "mma.sync.aligned.m16n8k8.row.col.f32.tf32.tf32.f32 "
      "{%0,%1,%2,%3}, {%4,%5,%6,%7}, {%8,%9}, {%0,%1,%2,%3};"
      : "+f"(d[0]), "+f"(d[1]), "+f"(d[2]), "+f"(d[3])
      : "r"(a[0]), "r"(a[1]), "r"(a[2]), "r"(a[3]), "r"(b[0]), "r"(b[1]));
}

__global__ __launch_bounds__(THREADS, 1)
void conv1d_tf32_w16(const float* __restrict__ x,
                     const float* __restrict__ w,
                     float* __restrict__ out) {
  extern __shared__ char smem[];
  float* sA = reinterpret_cast<float*>(smem);
  const uint32_t sBu = smem_u32(smem) + A_BYTES;

  const int tid = threadIdx.x;
  const int lane = tid & 31;
  const int wid = tid >> 5;
  const int b = blockIdx.y;
  const int p0 = blockIdx.x * TILE_P;

  // ------------------------------------------------------------------
  // Stage A (128x256 weights) once, fragment order, 1/sqrt(128) folded.
  // Slot (o,kidx): mt=o>>4, kt=kidx>>3, r=o&15, c=kidx&7
  //   lane=(r&7)*4+(c&3), reg=(r>>3)+((c>>2)<<1)
  //   float offset = (mt*32+kt)*128 + lane*4 + reg
  // ------------------------------------------------------------------
  const float scale = 0.08838834764831845f;
  #pragma unroll
  for (int it = 0; it < 16; ++it) {
    int lin = it * THREADS + tid;
    int o = lin >> 6;
    int j = lin & 63;
    float4 w4 = *reinterpret_cast<const float4*>(w + o * kK + 4 * j);
    float v[4] = {to_tf32(w4.x * scale), to_tf32(w4.y * scale),
                  to_tf32(w4.z * scale), to_tf32(w4.w * scale)};
    int mt = o >> 4, r = o & 15, kt = j >> 1;
    float* base = sA + (mt * 32 + kt) * 128;
    #pragma unroll
    for (int e = 0; e < 4; ++e) {
      int c = (4 * j + e) & 7;
      int ln = (r & 7) * 4 + (c & 3);
      int rg = (r >> 3) + ((c >> 2) << 1);
      base[ln * 4 + rg] = v[e];
    }
  }

  // ------------------------------------------------------------------
  // B chunk loader: chunk ch = c rows [16ch,16ch+16), 512 floats each.
  // 512 threads: row = (tid>>7) + 4q, col16 = tid&127. Odd rows XOR 64B.
  // ------------------------------------------------------------------
  const int ld_row_off = tid >> 7;            // 0..3
  const int ld_c16 = tid & 127;
  auto load_chunk = [&](int ch, int buf) {
    const float* xb =
        x + ((size_t)(b * kCin + ch * 16 + ld_row_off)) * kDin + 2 * p0 +
        4 * ld_c16;
    uint32_t d0 = sBu + (uint32_t)buf * B_STAGE +
                  (uint32_t)ld_row_off * ROWB +
                  ((uint32_t)(ld_c16 * 16) ^ ((uint32_t)(ld_row_off & 1) << 6));
    #pragma unroll
    for (int q = 0; q < 4; ++q) {     // rows ld_row_off + 4q (parity fixed)
      cp16(d0 + (uint32_t)(4 * q) * ROWB, xb + (size_t)(4 * q) * kDin);
    }
    cp_commit();
  };

  // ------------------------------------------------------------------
  // Warp tiling: 16 warps = 2(m) x 8(n), warp tile 64 x 32.
  // ------------------------------------------------------------------
  const int wm = (wid >> 3) * 64;            // 0 or 64
  const int wn = (wid & 7) * 32;             // 0..224
  const int gid = lane >> 2, tq = lane & 3;
  const float* sAw = sA + (wm >> 4) * 32 * 128;

  float acc[4][4][4];
  #pragma unroll
  for (int i = 0; i < 4; ++i)
    #pragma unroll
    for (int j2 = 0; j2 < 4; ++j2)
      #pragma unroll
      for (int r2 = 0; r2 < 4; ++r2) acc[i][j2][r2] = 0.f;

  // Per-lane B address pieces. Fragment (nt,k8):
  //   reg0: row 4k8+(tq>>1),   pos 2*(wn+8nt+gid)+(tq&1)
  //   reg1: row 4k8+(tq>>1)+2, same pos.  XOR 64 iff row odd ((tq>>1)&1).
  const uint32_t bpar = ((uint32_t)(tq >> 1) & 1u) << 6;
  const uint32_t brow0 = (uint32_t)(tq >> 1) * ROWB;
  const uint32_t bq0 = (uint32_t)(8 * (wn + gid) + 4 * (tq & 1));

  auto compute_chunk = [&](int ch, int buf) {
    const uint32_t bb = sBu + (uint32_t)buf * B_STAGE + brow0;
    #pragma unroll
    for (int k8 = 0; k8 < 4; ++k8) {
      const int kt = ch * 4 + k8;
      uint32_t afr[4][4];
      #pragma unroll
      for (int mt2 = 0; mt2 < 4; ++mt2) {
        uint4 av = *reinterpret_cast<const uint4*>(
            sAw + (mt2 * 32 + kt) * 128 + lane * 4);
        afr[mt2][0] = av.x; afr[mt2][1] = av.y;
        afr[mt2][2] = av.z; afr[mt2][3] = av.w;
      }
      const uint32_t rb = bb + (uint32_t)(4 * k8) * ROWB;
      uint32_t bfr[4][2];
      #pragma unroll
      for (int nt = 0; nt < 4; ++nt) {
        uint32_t loc = (bq0 + (uint32_t)(64 * nt)) ^ bpar;
        bfr[nt][0] = tf32u(lds32(rb + loc));
        bfr[nt][1] = tf32u(lds32(rb + 2u * ROWB + loc));
      }
      #pragma unroll
      for (int mt2 = 0; mt2 < 4; ++mt2)
        #pragma unroll
        for (int nt = 0; nt < 4; ++nt)
          mma_tf32(acc[mt2][nt], afr[mt2], bfr[nt]);
    }
  };

  // ------------------------------------------------------------------
  // 2-stage cp.async pipeline over 8 chunks.
  // ------------------------------------------------------------------
  load_chunk(0, 0);
  __syncthreads();      // A staging visible (and pipeline start)

  #pragma unroll 1
  for (int ch = 0; ch < NCH; ++ch) {
    if (ch + 1 < NCH) {
      load_chunk(ch + 1, (ch + 1) & 1);
      cp_wait<1>();
    } else {
      cp_wait<0>();
    }
    __syncthreads();
    compute_chunk(ch, ch & 1);
    __syncthreads();
  }

  // ------------------------------------------------------------------
  // Epilogue (scale already folded): float2 stores.
  // D frag: c0:(g,2tq) c1:(g,2tq+1) c2:(g+8,2tq) c3:(g+8,2tq+1)
  // ------------------------------------------------------------------
  float* ob = out + (size_t)b * kO * kP;
  #pragma unroll
  for (int mt2 = 0; mt2 < 4; ++mt2) {
    int o0 = wm + mt2 * 16 + gid;
    #pragma unroll
    for (int nt = 0; nt < 4; ++nt) {
      int p = p0 + wn + nt * 8 + 2 * tq;
      *reinterpret_cast<float2*>(ob + (size_t)o0 * kP + p) =
          make_float2(acc[mt2][nt][0], acc[mt2][nt][1]);
      *reinterpret_cast<float2*>(ob + (size_t)(o0 + 8) * kP + p) =
          make_float2(acc[mt2][nt][2], acc[mt2][nt][3]);
    }
  }
}

extern "C" void kernel_launch(void* const* d_in, const int* in_sizes, int n_in,
                              void* d_out, int out_size) {
  const float* x = (const float*)d_in[0];
  const float* w = (const float*)d_in[1];
  if (n_in >= 2 && in_sizes[0] == kO * kK) {   // defensive operand id by size
    const float* t = x; x = w; w = t;
  }
  (void)out_size;

  cudaFuncSetAttribute(conv1d_tf32_w16,
                       cudaFuncAttributeMaxDynamicSharedMemorySize, SMEM_BYTES);

  dim3 grid(kP / TILE_P, 32);   // (16, 32) = 512 CTAs
  conv1d_tf32_w16<<<grid, THREADS, SMEM_BYTES>>>(x, w, (float*)d_out);
}